// round 2
// baseline (speedup 1.0000x reference)
#include <cuda_runtime.h>
#include <cstdint>

// ---------------- Problem constants ----------------
#define HB   1024          // NUM_BASIC (K)
#define HM   8192          // NUM_MIXED (GEMM M)
#define RR   735           // T*7*7 rows of X (GEMM N, logical)
#define RPAD 768           // padded N
#define NN   57            // output matrix dim
#define OUTN (NN*NN)       // 3249

// ---------------- Scratch (device globals; no allocs allowed) ----------------
__device__ float g_X [RPAD * HB];              // 3 MB   : X (tf32-rounded), rows 735..767 zero
__device__ float g_Wt[HM * HB];                // 33.5 MB: W tf32-rounded (RNA)
__device__ float g_Y [(size_t)HM * RPAD];      // 25 MB  : relu(X@W^T + b), [hm][r]

// ---------------- helpers ----------------
__device__ __forceinline__ float tf32r(float x) {
    uint32_t u;
    asm("cvt.rna.tf32.f32 %0, %1;" : "=r"(u) : "f"(x));
    return __uint_as_float(u);
}

__device__ __forceinline__ void cp16(uint32_t s, const void* g) {
    asm volatile("cp.async.cg.shared.global [%0], [%1], 16;" :: "r"(s), "l"(g));
}

__device__ __forceinline__ void mma_tf32(float* c, const uint32_t* a, const uint32_t* b) {
    asm volatile(
        "mma.sync.aligned.m16n8k8.row.col.f32.tf32.tf32.f32 "
        "{%0,%1,%2,%3}, {%4,%5,%6,%7}, {%8,%9}, {%0,%1,%2,%3};"
        : "+f"(c[0]), "+f"(c[1]), "+f"(c[2]), "+f"(c[3])
        : "r"(a[0]), "r"(a[1]), "r"(a[2]), "r"(a[3]), "r"(b[0]), "r"(b[1]));
}

// ---------------- Kernel 1: RNA-round W to tf32 ----------------
__global__ void round_w_kernel(const float4* __restrict__ W) {
    int total = HM * HB / 4;
    float4* dst = reinterpret_cast<float4*>(g_Wt);
    for (int idx = blockIdx.x * blockDim.x + threadIdx.x; idx < total;
         idx += gridDim.x * blockDim.x) {
        float4 v = W[idx];
        v.x = tf32r(v.x); v.y = tf32r(v.y); v.z = tf32r(v.z); v.w = tf32r(v.w);
        dst[idx] = v;
    }
}

// ---------------- Kernel 2: build X (tf32-rounded) ----------------
// r = (t*7+m)*7 + n ; X[r,h] = (sigmoid(te[h,t])+1) * relu(mat[h,n,m])
__global__ void build_x_kernel(const float* __restrict__ mat, const float* __restrict__ te) {
    int r = blockIdx.x;
    if (r >= RR) {  // zero padding rows (deterministic)
        for (int h = threadIdx.x; h < HB; h += blockDim.x) g_X[r * HB + h] = 0.f;
        return;
    }
    int tm = r / 7, n = r % 7;
    int t  = tm / 7, m = tm % 7;
    for (int h = threadIdx.x; h < HB; h += blockDim.x) {
        float s  = 1.f + 1.f / (1.f + expf(-te[h * 15 + t]));
        float mv = mat[h * 49 + n * 7 + m];
        g_X[r * HB + h] = tf32r(s * fmaxf(mv, 0.f));
    }
}

// ---------------- Kernel 3: tf32 mma.sync GEMM ----------------
// C[M=8192(hm)][N=768(r)] = g_Wt @ g_X^T ; epilogue: relu(C + b[hm]) -> g_Y
#define KT 16          // K per smem stage
#define KS 20          // smem row stride (floats): g*20+t4 mod 32 -> conflict-free
#define KTILES (HB / KT)

__global__ __launch_bounds__(256, 2) void gemm_kernel(const float* __restrict__ bias) {
    __shared__ float As[2][128 * KS];
    __shared__ float Bs[2][128 * KS];

    const int tid  = threadIdx.x;
    const int lane = tid & 31, warp = tid >> 5;
    const int g  = lane >> 2, t4 = lane & 3;
    const int mb = (warp >> 1) * 32;   // warp grid 4(M) x 2(N)
    const int nb = (warp & 1) * 64;
    const int m0 = blockIdx.y * 128;
    const int n0 = blockIdx.x * 128;

    const int lrow = tid >> 2;            // 0..63
    const int lkq  = (tid & 3) * 4;       // 0,4,8,12

    uint32_t sA = (uint32_t)__cvta_generic_to_shared(&As[0][0]);
    uint32_t sB = (uint32_t)__cvta_generic_to_shared(&Bs[0][0]);

    const float* Ag = g_Wt + (size_t)m0 * HB;
    const float* Bg = g_X  + (size_t)n0 * HB;

    float c[2][8][4];
    #pragma unroll
    for (int i = 0; i < 2; i++)
        #pragma unroll
        for (int j = 0; j < 8; j++)
            #pragma unroll
            for (int q = 0; q < 4; q++) c[i][j][q] = 0.f;

    auto load_stage = [&](int s, int kt) {
        const int k0 = kt * KT;
        uint32_t sa = sA + (uint32_t)(s * (128 * KS)) * 4u;
        uint32_t sb = sB + (uint32_t)(s * (128 * KS)) * 4u;
        #pragma unroll
        for (int i = 0; i < 2; i++) {
            int row = lrow + i * 64;
            cp16(sa + (uint32_t)(row * KS + lkq) * 4u, Ag + (size_t)row * HB + k0 + lkq);
            cp16(sb + (uint32_t)(row * KS + lkq) * 4u, Bg + (size_t)row * HB + k0 + lkq);
        }
        asm volatile("cp.async.commit_group;");
    };

    load_stage(0, 0);

    #pragma unroll 1
    for (int kt = 0; kt < KTILES; kt++) {
        if (kt + 1 < KTILES) {
            load_stage((kt + 1) & 1, kt + 1);
            asm volatile("cp.async.wait_group 1;");
        } else {
            asm volatile("cp.async.wait_group 0;");
        }
        __syncthreads();

        const float* as = As[kt & 1];
        const float* bs = Bs[kt & 1];
        #pragma unroll
        for (int k8 = 0; k8 < 2; k8++) {
            const int kk = k8 * 8 + t4;
            uint32_t a[2][4], b[8][2];
            #pragma unroll
            for (int mt = 0; mt < 2; mt++) {
                int mr = (mb + mt * 16 + g) * KS + kk;
                a[mt][0] = __float_as_uint(as[mr]);
                a[mt][1] = __float_as_uint(as[mr + 8 * KS]);
                a[mt][2] = __float_as_uint(as[mr + 4]);
                a[mt][3] = __float_as_uint(as[mr + 8 * KS + 4]);
            }
            #pragma unroll
            for (int nt = 0; nt < 8; nt++) {
                int nr = (nb + nt * 8 + g) * KS + kk;
                b[nt][0] = __float_as_uint(bs[nr]);
                b[nt][1] = __float_as_uint(bs[nr + 4]);
            }
            #pragma unroll
            for (int mt = 0; mt < 2; mt++)
                #pragma unroll
                for (int nt = 0; nt < 8; nt++)
                    mma_tf32(c[mt][nt], a[mt], b[nt]);
        }
        __syncthreads();
    }

    // epilogue: +bias, relu, store Y[hm][r]
    #pragma unroll
    for (int mt = 0; mt < 2; mt++) {
        #pragma unroll
        for (int q = 0; q < 2; q++) {
            int row = m0 + mb + mt * 16 + g + q * 8;
            float bv = bias[row];
            #pragma unroll
            for (int nt = 0; nt < 8; nt++) {
                int col = n0 + nb + nt * 8 + t4 * 2;
                float2 v;
                v.x = fmaxf(c[mt][nt][q * 2 + 0] + bv, 0.f);
                v.y = fmaxf(c[mt][nt][q * 2 + 1] + bv, 0.f);
                *reinterpret_cast<float2*>(&g_Y[(size_t)row * RPAD + col]) = v;
            }
        }
    }
}

// ---------------- Kernel 4: assemble + degree-normalize ----------------
// mixed[hm,1+row,1+col] = Y[hm, (49-7*(row/7)+col)*7 + row%7]
// row 0 / col 0: identity entries at multiples of 7. d = clip(rowsum,1)^-0.5.
__global__ void assemble_kernel(float* __restrict__ out) {
    __shared__ float sy[RR + 1];
    __shared__ float sd[NN];
    const int hm = blockIdx.x;
    const float* yrow = g_Y + (size_t)hm * RPAD;

    for (int r = threadIdx.x; r < RR; r += blockDim.x) sy[r] = yrow[r];
    __syncthreads();

    if (threadIdx.x < NN) {
        int i = threadIdx.x;
        float s;
        if (i == 0) {
            s = 9.f;  // row 0: ones at cols 0,7,...,56
        } else {
            int row = i - 1, j = row / 7, n = row % 7;
            int base = (49 - 7 * j) * 7 + n;
            float acc = (n == 6) ? 1.f : 0.f;  // col-0 identity when i%7==0
            #pragma unroll
            for (int cc = 0; cc < 56; cc++) acc += sy[base + cc * 7];
            s = acc;
        }
        sd[i] = (s <= 1.f) ? 1.f : rsqrtf(s);
    }
    __syncthreads();

    const size_t ob = (size_t)hm * OUTN;
    for (int e = threadIdx.x; e < OUTN; e += blockDim.x) {
        int i = e / NN, jc = e - i * NN;
        float v;
        if (i == 0) {
            v = (jc % 7 == 0) ? sd[0] * sd[jc] : 0.f;
        } else if (jc == 0) {
            v = (i % 7 == 0) ? sd[i] * sd[0] : 0.f;
        } else {
            int row = i - 1, col = jc - 1;
            int j = row / 7, n = row % 7;
            v = sd[i] * sd[jc] * sy[(49 - 7 * j + col) * 7 + n];
        }
        out[ob + e] = v;
    }
}

// ---------------- launch ----------------
extern "C" void kernel_launch(void* const* d_in, const int* in_sizes, int n_in,
                              void* d_out, int out_size) {
    const float* mat = (const float*)d_in[0];
    const float* te  = (const float*)d_in[1];
    const float* W   = (const float*)d_in[2];
    const float* b   = (const float*)d_in[3];
    float* out = (float*)d_out;

    round_w_kernel<<<2048, 256>>>((const float4*)W);
    build_x_kernel<<<RPAD, 256>>>(mat, te);
    gemm_kernel<<<dim3(6, 64), 256>>>(b);
    assemble_kernel<<<HM, 256>>>(out);
}

// round 3
// speedup vs baseline: 1.3108x; 1.3108x over previous
#include <cuda_runtime.h>
#include <cstdint>

// ---------------- Problem constants ----------------
#define HB   1024          // NUM_BASIC (K)
#define HM   8192          // NUM_MIXED (GEMM M)
#define RR   735           // T*7*7 rows of X (GEMM N, logical)
#define RPAD 768           // padded N
#define NN   57            // output matrix dim
#define OUTN (NN*NN)       // 3249

// ---------------- Scratch (device globals; no allocs allowed) ----------------
__device__ float g_X [RPAD * HB];              // 3 MB  : X (tf32-rounded), rows 735..767 zero
__device__ float g_Y [(size_t)HM * RPAD];      // 25 MB : relu(X@W^T + b), [hm][r]

// ---------------- helpers ----------------
__device__ __forceinline__ float tf32r(float x) {
    uint32_t u;
    asm("cvt.rna.tf32.f32 %0, %1;" : "=r"(u) : "f"(x));
    return __uint_as_float(u);
}
__device__ __forceinline__ uint32_t tf32u(float x) {
    uint32_t u;
    asm("cvt.rna.tf32.f32 %0, %1;" : "=r"(u) : "f"(x));
    return u;
}

__device__ __forceinline__ void cp16(uint32_t s, const void* g) {
    asm volatile("cp.async.cg.shared.global [%0], [%1], 16;" :: "r"(s), "l"(g));
}

__device__ __forceinline__ void mma_tf32(float* c, const uint32_t* a, const uint32_t* b) {
    asm volatile(
        "mma.sync.aligned.m16n8k8.row.col.f32.tf32.tf32.f32 "
        "{%0,%1,%2,%3}, {%4,%5,%6,%7}, {%8,%9}, {%0,%1,%2,%3};"
        : "+f"(c[0]), "+f"(c[1]), "+f"(c[2]), "+f"(c[3])
        : "r"(a[0]), "r"(a[1]), "r"(a[2]), "r"(a[3]), "r"(b[0]), "r"(b[1]));
}

// ---------------- Kernel 1: build X (tf32-rounded) ----------------
// r = (t*7+m)*7 + n ; X[r,h] = (sigmoid(te[h,t])+1) * relu(mat[h,n,m])
__global__ void build_x_kernel(const float* __restrict__ mat, const float* __restrict__ te) {
    int r = blockIdx.x;
    if (r >= RR) {  // zero padding rows (deterministic)
        for (int h = threadIdx.x; h < HB; h += blockDim.x) g_X[r * HB + h] = 0.f;
        return;
    }
    int tm = r / 7, n = r % 7;
    int t  = tm / 7, m = tm % 7;
    for (int h = threadIdx.x; h < HB; h += blockDim.x) {
        float s  = 1.f + 1.f / (1.f + expf(-te[h * 15 + t]));
        float mv = mat[h * 49 + n * 7 + m];
        g_X[r * HB + h] = tf32r(s * fmaxf(mv, 0.f));
    }
}

// ---------------- Kernel 2: tf32 mma.sync GEMM ----------------
// C[M=8192(hm)][N=768(r)] = W @ g_X^T ; A-fragments RNA-rounded in-register.
// epilogue: relu(C + b[hm]) -> g_Y
#define KT 16          // K per smem stage
#define KS 20          // smem row stride (floats): g*20+t4 mod 32 -> conflict-free
#define KTILES (HB / KT)

__global__ __launch_bounds__(256, 2) void gemm_kernel(const float* __restrict__ Wg,
                                                      const float* __restrict__ bias) {
    __shared__ float As[2][128 * KS];
    __shared__ float Bs[2][128 * KS];

    const int tid  = threadIdx.x;
    const int lane = tid & 31, warp = tid >> 5;
    const int g  = lane >> 2, t4 = lane & 3;
    const int mb = (warp >> 1) * 32;   // warp grid 4(M) x 2(N)
    const int nb = (warp & 1) * 64;
    const int m0 = blockIdx.y * 128;
    const int n0 = blockIdx.x * 128;

    const int lrow = tid >> 2;            // 0..63
    const int lkq  = (tid & 3) * 4;       // 0,4,8,12

    uint32_t sA = (uint32_t)__cvta_generic_to_shared(&As[0][0]);
    uint32_t sB = (uint32_t)__cvta_generic_to_shared(&Bs[0][0]);

    const float* Ag = Wg  + (size_t)m0 * HB;   // raw fp32 W
    const float* Bg = g_X + (size_t)n0 * HB;   // pre-rounded X

    float c[2][8][4];
    #pragma unroll
    for (int i = 0; i < 2; i++)
        #pragma unroll
        for (int j = 0; j < 8; j++)
            #pragma unroll
            for (int q = 0; q < 4; q++) c[i][j][q] = 0.f;

    auto load_stage = [&](int s, int kt) {
        const int k0 = kt * KT;
        uint32_t sa = sA + (uint32_t)(s * (128 * KS)) * 4u;
        uint32_t sb = sB + (uint32_t)(s * (128 * KS)) * 4u;
        #pragma unroll
        for (int i = 0; i < 2; i++) {
            int row = lrow + i * 64;
            cp16(sa + (uint32_t)(row * KS + lkq) * 4u, Ag + (size_t)row * HB + k0 + lkq);
            cp16(sb + (uint32_t)(row * KS + lkq) * 4u, Bg + (size_t)row * HB + k0 + lkq);
        }
        asm volatile("cp.async.commit_group;");
    };

    load_stage(0, 0);

    #pragma unroll 1
    for (int kt = 0; kt < KTILES; kt++) {
        if (kt + 1 < KTILES) {
            load_stage((kt + 1) & 1, kt + 1);
            asm volatile("cp.async.wait_group 1;");
        } else {
            asm volatile("cp.async.wait_group 0;");
        }
        __syncthreads();

        const float* as = As[kt & 1];
        const float* bs = Bs[kt & 1];
        #pragma unroll
        for (int k8 = 0; k8 < 2; k8++) {
            const int kk = k8 * 8 + t4;
            uint32_t a[2][4], b[8][2];
            #pragma unroll
            for (int mt = 0; mt < 2; mt++) {
                int mr = (mb + mt * 16 + g) * KS + kk;
                a[mt][0] = tf32u(as[mr]);                 // RNA round W in-register
                a[mt][1] = tf32u(as[mr + 8 * KS]);
                a[mt][2] = tf32u(as[mr + 4]);
                a[mt][3] = tf32u(as[mr + 8 * KS + 4]);
            }
            #pragma unroll
            for (int nt = 0; nt < 8; nt++) {
                int nr = (nb + nt * 8 + g) * KS + kk;
                b[nt][0] = __float_as_uint(bs[nr]);       // X already rounded
                b[nt][1] = __float_as_uint(bs[nr + 4]);
            }
            #pragma unroll
            for (int mt = 0; mt < 2; mt++)
                #pragma unroll
                for (int nt = 0; nt < 8; nt++)
                    mma_tf32(c[mt][nt], a[mt], b[nt]);
        }
        __syncthreads();
    }

    // epilogue: +bias, relu, store Y[hm][r]
    #pragma unroll
    for (int mt = 0; mt < 2; mt++) {
        #pragma unroll
        for (int q = 0; q < 2; q++) {
            int row = m0 + mb + mt * 16 + g + q * 8;
            float bv = bias[row];
            #pragma unroll
            for (int nt = 0; nt < 8; nt++) {
                int col = n0 + nb + nt * 8 + t4 * 2;
                float2 v;
                v.x = fmaxf(c[mt][nt][q * 2 + 0] + bv, 0.f);
                v.y = fmaxf(c[mt][nt][q * 2 + 1] + bv, 0.f);
                *reinterpret_cast<float2*>(&g_Y[(size_t)row * RPAD + col]) = v;
            }
        }
    }
}

// ---------------- Kernel 3: assemble + degree-normalize (div/mod-free hot loop) ----------------
// mixed[hm,1+row,1+col] = Y[hm, (49-7*(row/7)+col)*7 + row%7]
// row 0 / col 0: identity entries at multiples of 7. d = clip(rowsum,1)^-0.5.
// Block = 228 threads = (jc in 0..56) x (ty in 0..3). All div/mod hoisted out of the
// per-element loop; gather index is rbase[i] + (jc-1)*7 (stride-7 LDS: conflict-free).
__global__ __launch_bounds__(228) void assemble_kernel(float* __restrict__ out) {
    __shared__ float sy[RR + 1];
    __shared__ float sd[NN];
    __shared__ float psum[4][NN + 1];
    __shared__ int   rbase[NN];

    const int tid = threadIdx.x;
    const int jc  = tid % 57;     // computed once per thread
    const int ty  = tid / 57;     // 0..3
    const int hm  = blockIdx.x;
    const float* yrow = g_Y + (size_t)hm * RPAD;

    for (int r = tid; r < RR; r += 228) sy[r] = yrow[r];
    if (tid > 0 && tid < NN) {
        int row = tid - 1, j = row / 7, n = row % 7;
        rbase[tid] = (49 - 7 * j) * 7 + n;
    }
    __syncthreads();

    // partial row sums: row i summed by 4 threads (ty = quarter), 14 terms each
    {
        float acc = 0.f;
        if (jc > 0) {
            int base = rbase[jc] + ty * 14 * 7;
            #pragma unroll
            for (int cc = 0; cc < 14; cc++) acc += sy[base + cc * 7];
        }
        psum[ty][jc] = acc;
    }
    __syncthreads();

    if (tid < NN) {
        float s;
        if (tid == 0) {
            s = 9.f;  // row 0: ones at cols 0,7,...,56
        } else {
            s = psum[0][tid] + psum[1][tid] + psum[2][tid] + psum[3][tid];
            if ((tid % 7) == 0) s += 1.f;   // col-0 identity when i%7==0  (n==6)
        }
        sd[tid] = (s <= 1.f) ? 1.f : rsqrtf(s);
    }
    __syncthreads();

    const size_t ob  = (size_t)hm * OUTN;
    const float  sdj = sd[jc];
    const bool   jc7 = (jc % 7) == 0;     // once per thread
    const int    gcol = (jc - 1) * 7;

    #pragma unroll
    for (int it = 0; it < 15; it++) {
        int i = ty + it * 4;
        if (i >= NN) break;
        float v;
        if (i == 0) {
            v = jc7 ? sd[0] * sdj : 0.f;
        } else if (jc == 0) {
            v = ((i % 7) == 0) ? sd[i] * sd[0] : 0.f;   // only 4 threads/block hit this
        } else {
            v = sd[i] * sdj * sy[rbase[i] + gcol];
        }
        out[ob + i * NN + jc] = v;
    }
}

// ---------------- launch ----------------
extern "C" void kernel_launch(void* const* d_in, const int* in_sizes, int n_in,
                              void* d_out, int out_size) {
    const float* mat = (const float*)d_in[0];
    const float* te  = (const float*)d_in[1];
    const float* W   = (const float*)d_in[2];
    const float* b   = (const float*)d_in[3];
    float* out = (float*)d_out;

    build_x_kernel<<<RPAD, 256>>>(mat, te);
    gemm_kernel<<<dim3(6, 64), 256>>>(W, b);
    assemble_kernel<<<HM, 228>>>(out);
}

// round 6
// speedup vs baseline: 1.3249x; 1.0108x over previous
#include <cuda_runtime.h>
#include <cstdint>

// ---------------- Problem constants ----------------
#define HB   1024          // NUM_BASIC (K)
#define HM   8192          // NUM_MIXED (GEMM M)
#define RR   735           // T*7*7 rows of X (GEMM N, logical)
#define RPAD 768           // padded N
#define NN   57            // output matrix dim
#define OUTN (NN*NN)       // 3249

// ---------------- Scratch (device globals; no allocs allowed) ----------------
__device__ float g_X [RPAD * HB];              // 3 MB  : X (tf32-rounded), rows 735..767 zero
__device__ float g_Y [(size_t)HM * RPAD];      // 25 MB : relu(X@W^T + b), [hm][r]

// ---------------- helpers ----------------
__device__ __forceinline__ float tf32r(float x) {
    uint32_t u;
    asm("cvt.rna.tf32.f32 %0, %1;" : "=r"(u) : "f"(x));
    return __uint_as_float(u);
}
__device__ __forceinline__ uint32_t tf32u(float x) {
    uint32_t u;
    asm("cvt.rna.tf32.f32 %0, %1;" : "=r"(u) : "f"(x));
    return u;
}
__device__ __forceinline__ void cp16(uint32_t s, const void* g) {
    asm volatile("cp.async.cg.shared.global [%0], [%1], 16;" :: "r"(s), "l"(g));
}
__device__ __forceinline__ void mma_tf32(float* c, const uint32_t* a, const uint32_t* b) {
    asm volatile(
        "mma.sync.aligned.m16n8k8.row.col.f32.tf32.tf32.f32 "
        "{%0,%1,%2,%3}, {%4,%5,%6,%7}, {%8,%9}, {%0,%1,%2,%3};"
        : "+f"(c[0]), "+f"(c[1]), "+f"(c[2]), "+f"(c[3])
        : "r"(a[0]), "r"(a[1]), "r"(a[2]), "r"(a[3]), "r"(b[0]), "r"(b[1]));
}

// ---------------- Kernel 1: build X (tf32-rounded), low-latency form ----------------
// Block p in 0..48 -> (m = p/7, n = p%7); handles all 15 t and 512 h per blockIdx.y.
// r = (t*7+m)*7 + n ; X[r,h] = (sigmoid(te[h,t])+1) * relu(mat[h,n,m])
// Block p == 49 zeroes the padding rows 735..767.
__global__ __launch_bounds__(512) void build_x_kernel(const float* __restrict__ mat,
                                                      const float* __restrict__ te) {
    const int p = blockIdx.x;
    const int h = blockIdx.y * 512 + threadIdx.x;
    if (p == 49) {  // zero padding rows
        #pragma unroll
        for (int row = RR; row < RPAD; row++) g_X[row * HB + h] = 0.f;
        return;
    }
    const int m = p / 7, n = p % 7;
    const float mv = fmaxf(mat[h * 49 + n * 7 + m], 0.f);
    const int rb = m * 7 + n;
    #pragma unroll
    for (int t = 0; t < 15; t++) {
        float s = 1.f + 1.f / (1.f + __expf(-te[h * 15 + t]));
        g_X[(t * 49 + rb) * HB + h] = tf32r(s * mv);
    }
}

// ---------------- Kernel 2: tf32 mma.sync GEMM, 3-stage pipeline ----------------
// C[M=8192(hm)][N=768(r)] = W @ g_X^T ; A-fragments RNA-rounded in-register.
// epilogue: relu(C + b[hm]) -> g_Y
#define KT 16            // K per smem stage
#define KS 20            // smem row stride (floats): g*20+t4 mod 32 -> conflict-free
#define KTILES (HB / KT) // 64
#define NSTAGE 3
#define STAGE_F (128 * KS)            // floats per array per stage
#define GEMM_DYN (NSTAGE * 2 * STAGE_F * 4)   // 61440 bytes

extern __shared__ float g_sm[];

__global__ __launch_bounds__(256, 2) void gemm_kernel(const float* __restrict__ Wg,
                                                      const float* __restrict__ bias) {
    const int tid  = threadIdx.x;
    const int lane = tid & 31, warp = tid >> 5;
    const int g  = lane >> 2, t4 = lane & 3;
    const int mb = (warp >> 1) * 32;   // warp grid 4(M) x 2(N)
    const int nb = (warp & 1) * 64;
    const int m0 = blockIdx.y * 128;
    const int n0 = blockIdx.x * 128;

    const int lrow = tid >> 2;            // 0..63
    const int lkq  = (tid & 3) * 4;       // 0,4,8,12

    const uint32_t sBase = (uint32_t)__cvta_generic_to_shared(g_sm);

    const float* Ag = Wg  + (size_t)m0 * HB;   // raw fp32 W
    const float* Bg = g_X + (size_t)n0 * HB;   // pre-rounded X

    float c[2][8][4];
    #pragma unroll
    for (int i = 0; i < 2; i++)
        #pragma unroll
        for (int j = 0; j < 8; j++)
            #pragma unroll
            for (int q = 0; q < 4; q++) c[i][j][q] = 0.f;

    auto load_stage = [&](int s, int kt) {
        const int k0 = kt * KT;
        uint32_t sa = sBase + (uint32_t)(s * (2 * STAGE_F)) * 4u;
        uint32_t sb = sa + (uint32_t)STAGE_F * 4u;
        #pragma unroll
        for (int i = 0; i < 2; i++) {
            int row = lrow + i * 64;
            cp16(sa + (uint32_t)(row * KS + lkq) * 4u, Ag + (size_t)row * HB + k0 + lkq);
            cp16(sb + (uint32_t)(row * KS + lkq) * 4u, Bg + (size_t)row * HB + k0 + lkq);
        }
        asm volatile("cp.async.commit_group;");
    };

    load_stage(0, 0);
    load_stage(1, 1);

    #pragma unroll 1
    for (int kt = 0; kt < KTILES; kt++) {
        if (kt < KTILES - 2) asm volatile("cp.async.wait_group 1;");
        else                 asm volatile("cp.async.wait_group 0;");
        __syncthreads();
        // prefetch stage kt+2 into the buffer freed by the barrier above
        int cur = kt % NSTAGE;
        if (kt + 2 < KTILES) load_stage((kt + 2) % NSTAGE, kt + 2);

        const float* as = g_sm + cur * (2 * STAGE_F);
        const float* bs = as + STAGE_F;
        #pragma unroll
        for (int k8 = 0; k8 < 2; k8++) {
            const int kk = k8 * 8 + t4;
            uint32_t a[2][4], b[8][2];
            #pragma unroll
            for (int mt = 0; mt < 2; mt++) {
                int mr = (mb + mt * 16 + g) * KS + kk;
                a[mt][0] = tf32u(as[mr]);                 // RNA round W in-register
                a[mt][1] = tf32u(as[mr + 8 * KS]);
                a[mt][2] = tf32u(as[mr + 4]);
                a[mt][3] = tf32u(as[mr + 8 * KS + 4]);
            }
            #pragma unroll
            for (int nt = 0; nt < 8; nt++) {
                int nr = (nb + nt * 8 + g) * KS + kk;
                b[nt][0] = __float_as_uint(bs[nr]);       // X already rounded
                b[nt][1] = __float_as_uint(bs[nr + 4]);
            }
            #pragma unroll
            for (int mt = 0; mt < 2; mt++)
                #pragma unroll
                for (int nt = 0; nt < 8; nt++)
                    mma_tf32(c[mt][nt], a[mt], b[nt]);
        }
    }

    // epilogue: +bias, relu, store Y[hm][r]
    #pragma unroll
    for (int mt = 0; mt < 2; mt++) {
        #pragma unroll
        for (int q = 0; q < 2; q++) {
            int row = m0 + mb + mt * 16 + g + q * 8;
            float bv = bias[row];
            #pragma unroll
            for (int nt = 0; nt < 8; nt++) {
                int col = n0 + nb + nt * 8 + t4 * 2;
                float2 v;
                v.x = fmaxf(c[mt][nt][q * 2 + 0] + bv, 0.f);
                v.y = fmaxf(c[mt][nt][q * 2 + 1] + bv, 0.f);
                *reinterpret_cast<float2*>(&g_Y[(size_t)row * RPAD + col]) = v;
            }
        }
    }
}

// ---------------- Kernel 3: assemble + degree-normalize (div/mod-free hot loop) ----------------
// mixed[hm,1+row,1+col] = Y[hm, (49-7*(row/7)+col)*7 + row%7]
// row 0 / col 0: identity entries at multiples of 7. d = clip(rowsum,1)^-0.5.
__global__ __launch_bounds__(228) void assemble_kernel(float* __restrict__ out) {
    __shared__ float sy[RR + 1];
    __shared__ float sd[NN];
    __shared__ float psum[4][NN + 1];
    __shared__ int   rbase[NN];

    const int tid = threadIdx.x;
    const int jc  = tid % 57;
    const int ty  = tid / 57;
    const int hm  = blockIdx.x;
    const float* yrow = g_Y + (size_t)hm * RPAD;

    for (int r = tid; r < RR; r += 228) sy[r] = yrow[r];
    if (tid > 0 && tid < NN) {
        int row = tid - 1, j = row / 7, n = row % 7;
        rbase[tid] = (49 - 7 * j) * 7 + n;
    }
    __syncthreads();

    {
        float acc = 0.f;
        if (jc > 0) {
            int base = rbase[jc] + ty * 14 * 7;
            #pragma unroll
            for (int cc = 0; cc < 14; cc++) acc += sy[base + cc * 7];
        }
        psum[ty][jc] = acc;
    }
    __syncthreads();

    if (tid < NN) {
        float s;
        if (tid == 0) s = 9.f;
        else {
            s = psum[0][tid] + psum[1][tid] + psum[2][tid] + psum[3][tid];
            if ((tid % 7) == 0) s += 1.f;
        }
        sd[tid] = (s <= 1.f) ? 1.f : rsqrtf(s);
    }
    __syncthreads();

    const size_t ob  = (size_t)hm * OUTN;
    const float  sdj = sd[jc];
    const bool   jc7 = (jc % 7) == 0;
    const int    gcol = (jc - 1) * 7;

    #pragma unroll
    for (int it = 0; it < 15; it++) {
        int i = ty + it * 4;
        if (i >= NN) break;
        float v;
        if (i == 0)        v = jc7 ? sd[0] * sdj : 0.f;
        else if (jc == 0)  v = ((i % 7) == 0) ? sd[i] * sd[0] : 0.f;
        else               v = sd[i] * sdj * sy[rbase[i] + gcol];
        out[ob + i * NN + jc] = v;
    }
}

// ---------------- launch ----------------
extern "C" void kernel_launch(void* const* d_in, const int* in_sizes, int n_in,
                              void* d_out, int out_size) {
    const float* mat = (const float*)d_in[0];
    const float* te  = (const float*)d_in[1];
    const float* W   = (const float*)d_in[2];
    const float* b   = (const float*)d_in[3];
    float* out = (float*)d_out;

    static int attr_set = 0;
    if (!attr_set) {
        cudaFuncSetAttribute(gemm_kernel, cudaFuncAttributeMaxDynamicSharedMemorySize, GEMM_DYN);
        attr_set = 1;
    }

    build_x_kernel<<<dim3(50, 2), 512>>>(mat, te);
    gemm_kernel<<<dim3(6, 64), 256, GEMM_DYN>>>(W, b);
    assemble_kernel<<<HM, 228>>>(out);
}

// round 7
// speedup vs baseline: 1.7378x; 1.3117x over previous
#include <cuda_runtime.h>
#include <cuda_fp16.h>
#include <cstdint>

// ---------------- Problem constants ----------------
#define HB   1024          // NUM_BASIC (K)
#define HM   8192          // NUM_MIXED (GEMM M)
#define RR   735           // T*7*7 rows of X (GEMM N, logical)
#define RPAD 768           // padded N
#define NN   57            // output matrix dim
#define OUTN (NN*NN)       // 3249

// ---------------- Scratch (device globals; no allocs allowed) ----------------
__device__ __half g_Xh[RPAD * HB];             // 1.5 MB : X in fp16, rows 735..767 zero
__device__ __half g_Wh[HM * HB];               // 16.7 MB: W in fp16 (RN)
__device__ float  g_Y [(size_t)HM * RPAD];     // 25 MB  : relu(X@W^T + b), [hm][r]

// ---------------- helpers ----------------
__device__ __forceinline__ void cp16(uint32_t s, const void* g) {
    asm volatile("cp.async.cg.shared.global [%0], [%1], 16;" :: "r"(s), "l"(g));
}
__device__ __forceinline__ void mma_f16(float* c, const uint32_t* a, const uint32_t* b) {
    asm volatile(
        "mma.sync.aligned.m16n8k16.row.col.f32.f16.f16.f32 "
        "{%0,%1,%2,%3}, {%4,%5,%6,%7}, {%8,%9}, {%0,%1,%2,%3};"
        : "+f"(c[0]), "+f"(c[1]), "+f"(c[2]), "+f"(c[3])
        : "r"(a[0]), "r"(a[1]), "r"(a[2]), "r"(a[3]), "r"(b[0]), "r"(b[1]));
}

// ---------------- Kernel 1: convert W to fp16 (RN) ----------------
// 8 floats -> 8 halfs per thread (16B read x2, 16B write)
__global__ void convert_w_kernel(const float4* __restrict__ W) {
    int i = blockIdx.x * blockDim.x + threadIdx.x;   // 0 .. HM*HB/8-1
    float4 v0 = W[i * 2];
    float4 v1 = W[i * 2 + 1];
    __half2 h[4];
    h[0] = __floats2half2_rn(v0.x, v0.y);
    h[1] = __floats2half2_rn(v0.z, v0.w);
    h[2] = __floats2half2_rn(v1.x, v1.y);
    h[3] = __floats2half2_rn(v1.z, v1.w);
    *reinterpret_cast<uint4*>(&g_Wh[(size_t)i * 8]) = *reinterpret_cast<uint4*>(h);
}

// ---------------- Kernel 2: build X in fp16 ----------------
// Block p in 0..48 -> (m = p/7, n = p%7); r = (t*7+m)*7 + n
// X[r,h] = (sigmoid(te[h,t])+1) * relu(mat[h,n,m]); p==49 zeroes padding rows.
__global__ __launch_bounds__(512) void build_x_kernel(const float* __restrict__ mat,
                                                      const float* __restrict__ te) {
    const int p = blockIdx.x;
    const int h = blockIdx.y * 512 + threadIdx.x;
    if (p == 49) {
        #pragma unroll
        for (int row = RR; row < RPAD; row++) g_Xh[row * HB + h] = __ushort_as_half(0);
        return;
    }
    const int m = p / 7, n = p % 7;
    const float mv = fmaxf(mat[h * 49 + n * 7 + m], 0.f);
    const int rb = m * 7 + n;
    #pragma unroll
    for (int t = 0; t < 15; t++) {
        float s = 1.f + 1.f / (1.f + __expf(-te[h * 15 + t]));
        g_Xh[(t * 49 + rb) * HB + h] = __float2half_rn(s * mv);
    }
}

// ---------------- Kernel 3: fp16 mma.sync GEMM, 3-stage pipeline ----------------
// C[M=8192(hm)][N=768(r)] = g_Wh @ g_Xh^T ; epilogue: relu(C + b[hm]) -> g_Y
#define KTH 32             // K halfs per smem stage
#define KSH 40             // smem row stride in halfs: bank=(20*row+t4)%32 conflict-free
#define KTILES (HB / KTH)  // 32
#define NSTAGE 3
#define STAGE_H (128 * KSH)                 // halfs per array per stage
#define GEMM_DYN (NSTAGE * 2 * STAGE_H * 2) // 61440 bytes

extern __shared__ __half g_sm[];

__global__ __launch_bounds__(256, 2) void gemm_kernel(const float* __restrict__ bias) {
    const int tid  = threadIdx.x;
    const int lane = tid & 31, warp = tid >> 5;
    const int g  = lane >> 2, t4 = lane & 3;
    const int mb = (warp >> 1) * 32;   // warp grid 4(M) x 2(N)
    const int nb = (warp & 1) * 64;
    const int m0 = blockIdx.y * 128;
    const int n0 = blockIdx.x * 128;

    const int lrow = tid >> 1;            // 0..127
    const int lkc  = (tid & 1) * 2;       // chunk pair {0,1} or {2,3}; chunk = 8 halfs

    const uint32_t sBase = (uint32_t)__cvta_generic_to_shared(g_sm);

    const __half* Ag = g_Wh + (size_t)(m0 + lrow) * HB;
    const __half* Bg = g_Xh + (size_t)(n0 + lrow) * HB;

    float c[2][8][4];
    #pragma unroll
    for (int i = 0; i < 2; i++)
        #pragma unroll
        for (int j = 0; j < 8; j++)
            #pragma unroll
            for (int q = 0; q < 4; q++) c[i][j][q] = 0.f;

    auto load_stage = [&](int s, int kt) {
        const int k0 = kt * KTH;
        uint32_t sa = sBase + (uint32_t)(s * (2 * STAGE_H)) * 2u;
        uint32_t sb = sa + (uint32_t)STAGE_H * 2u;
        #pragma unroll
        for (int cch = 0; cch < 2; cch++) {
            int kh = (lkc + cch) * 8;
            cp16(sa + (uint32_t)(lrow * KSH + kh) * 2u, Ag + k0 + kh);
            cp16(sb + (uint32_t)(lrow * KSH + kh) * 2u, Bg + k0 + kh);
        }
        asm volatile("cp.async.commit_group;");
    };

    load_stage(0, 0);
    load_stage(1, 1);

    #pragma unroll 1
    for (int kt = 0; kt < KTILES; kt++) {
        if (kt < KTILES - 2) asm volatile("cp.async.wait_group 1;");
        else                 asm volatile("cp.async.wait_group 0;");
        __syncthreads();
        int cur = kt % NSTAGE;
        if (kt + 2 < KTILES) load_stage((kt + 2) % NSTAGE, kt + 2);

        const __half* as = g_sm + cur * (2 * STAGE_H);
        const __half* bs = as + STAGE_H;
        #pragma unroll
        for (int s16 = 0; s16 < 2; s16++) {
            const int kh = s16 * 16 + 2 * t4;
            uint32_t a[2][4], b[8][2];
            #pragma unroll
            for (int mt = 0; mt < 2; mt++) {
                const __half* ap = as + (mb + mt * 16 + g) * KSH + kh;
                a[mt][0] = *reinterpret_cast<const uint32_t*>(ap);
                a[mt][1] = *reinterpret_cast<const uint32_t*>(ap + 8 * KSH);
                a[mt][2] = *reinterpret_cast<const uint32_t*>(ap + 8);
                a[mt][3] = *reinterpret_cast<const uint32_t*>(ap + 8 * KSH + 8);
            }
            #pragma unroll
            for (int nt = 0; nt < 8; nt++) {
                const __half* bp = bs + (nb + nt * 8 + g) * KSH + kh;
                b[nt][0] = *reinterpret_cast<const uint32_t*>(bp);
                b[nt][1] = *reinterpret_cast<const uint32_t*>(bp + 8);
            }
            #pragma unroll
            for (int mt = 0; mt < 2; mt++)
                #pragma unroll
                for (int nt = 0; nt < 8; nt++)
                    mma_f16(c[mt][nt], a[mt], b[nt]);
        }
    }

    // epilogue: +bias, relu, store Y[hm][r]
    #pragma unroll
    for (int mt = 0; mt < 2; mt++) {
        #pragma unroll
        for (int q = 0; q < 2; q++) {
            int row = m0 + mb + mt * 16 + g + q * 8;
            float bv = bias[row];
            #pragma unroll
            for (int nt = 0; nt < 8; nt++) {
                int col = n0 + nb + nt * 8 + t4 * 2;
                float2 v;
                v.x = fmaxf(c[mt][nt][q * 2 + 0] + bv, 0.f);
                v.y = fmaxf(c[mt][nt][q * 2 + 1] + bv, 0.f);
                *reinterpret_cast<float2*>(&g_Y[(size_t)row * RPAD + col]) = v;
            }
        }
    }
}

// ---------------- Kernel 4: assemble + degree-normalize ----------------
// mixed[hm,1+row,1+col] = Y[hm, (49-7*(row/7)+col)*7 + row%7]
// row 0 / col 0: identity entries at multiples of 7. d = clip(rowsum,1)^-0.5.
__global__ __launch_bounds__(228) void assemble_kernel(float* __restrict__ out) {
    __shared__ float sy[RR + 1];
    __shared__ float sd[NN];
    __shared__ float psum[4][NN + 1];
    __shared__ int   rbase[NN];

    const int tid = threadIdx.x;
    const int jc  = tid % 57;
    const int ty  = tid / 57;
    const int hm  = blockIdx.x;
    const float* yrow = g_Y + (size_t)hm * RPAD;

    for (int r = tid; r < RR; r += 228) sy[r] = yrow[r];
    if (tid > 0 && tid < NN) {
        int row = tid - 1, j = row / 7, n = row % 7;
        rbase[tid] = (49 - 7 * j) * 7 + n;
    }
    __syncthreads();

    {
        float acc = 0.f;
        if (jc > 0) {
            int base = rbase[jc] + ty * 14 * 7;
            #pragma unroll
            for (int cc = 0; cc < 14; cc++) acc += sy[base + cc * 7];
        }
        psum[ty][jc] = acc;
    }
    __syncthreads();

    if (tid < NN) {
        float s;
        if (tid == 0) s = 9.f;
        else {
            s = psum[0][tid] + psum[1][tid] + psum[2][tid] + psum[3][tid];
            if ((tid % 7) == 0) s += 1.f;
        }
        sd[tid] = (s <= 1.f) ? 1.f : rsqrtf(s);
    }
    __syncthreads();

    const size_t ob  = (size_t)hm * OUTN;
    const float  sdj = sd[jc];
    const bool   jc7 = (jc % 7) == 0;
    const int    gcol = (jc - 1) * 7;

    #pragma unroll
    for (int it = 0; it < 15; it++) {
        int i = ty + it * 4;
        if (i >= NN) break;
        float v;
        if (i == 0)        v = jc7 ? sd[0] * sdj : 0.f;
        else if (jc == 0)  v = ((i % 7) == 0) ? sd[i] * sd[0] : 0.f;
        else               v = sd[i] * sdj * sy[rbase[i] + gcol];
        out[ob + i * NN + jc] = v;
    }
}

// ---------------- launch ----------------
extern "C" void kernel_launch(void* const* d_in, const int* in_sizes, int n_in,
                              void* d_out, int out_size) {
    const float* mat = (const float*)d_in[0];
    const float* te  = (const float*)d_in[1];
    const float* W   = (const float*)d_in[2];
    const float* b   = (const float*)d_in[3];
    float* out = (float*)d_out;

    cudaFuncSetAttribute(gemm_kernel, cudaFuncAttributeMaxDynamicSharedMemorySize, GEMM_DYN);

    convert_w_kernel<<<HM * HB / 8 / 256, 256>>>((const float4*)W);
    build_x_kernel<<<dim3(50, 2), 512>>>(mat, te);
    gemm_kernel<<<dim3(6, 64), 256, GEMM_DYN>>>(b);
    assemble_kernel<<<HM, 228>>>(out);
}

// round 8
// speedup vs baseline: 1.8382x; 1.0577x over previous
#include <cuda_runtime.h>
#include <cuda_fp16.h>
#include <cstdint>

// ---------------- Problem constants ----------------
#define HB   1024          // NUM_BASIC (K)
#define HM   8192          // NUM_MIXED (GEMM M)
#define RR   735           // T*7*7 rows of X (GEMM N, logical)
#define RPAD 768           // padded N
#define NN   57            // output matrix dim
#define OUTN (NN*NN)       // 3249

// ---------------- Scratch (device globals; no allocs allowed) ----------------
__device__ __half g_Xh[RPAD * HB];             // 1.5 MB : X in fp16, rows 735..767 zero
__device__ __half g_Wh[HM * HB];               // 16.7 MB: W in fp16 (RN)
__device__ float  g_Y [(size_t)HM * RPAD];     // 25 MB  : relu(X@W^T + b), [hm][r]

// ---------------- helpers ----------------
__device__ __forceinline__ void cp16(uint32_t s, const void* g) {
    asm volatile("cp.async.cg.shared.global [%0], [%1], 16;" :: "r"(s), "l"(g));
}
__device__ __forceinline__ void mma_f16(float* c, const uint32_t* a, const uint32_t* b) {
    asm volatile(
        "mma.sync.aligned.m16n8k16.row.col.f32.f16.f16.f32 "
        "{%0,%1,%2,%3}, {%4,%5,%6,%7}, {%8,%9}, {%0,%1,%2,%3};"
        : "+f"(c[0]), "+f"(c[1]), "+f"(c[2]), "+f"(c[3])
        : "r"(a[0]), "r"(a[1]), "r"(a[2]), "r"(a[3]), "r"(b[0]), "r"(b[1]));
}
__device__ __forceinline__ void ldsm4(uint32_t* r, uint32_t addr) {
    asm volatile("ldmatrix.sync.aligned.m8n8.x4.shared.b16 {%0,%1,%2,%3}, [%4];"
        : "=r"(r[0]), "=r"(r[1]), "=r"(r[2]), "=r"(r[3]) : "r"(addr));
}

// ---------------- Kernel 1: fused prep (convert W + build X) ----------------
// blocks 0..99      : build_x  (p = b>>1 in 0..49, h-half = b&1)
// blocks 100..2147  : convert_w (512 threads x 8 floats)
__global__ __launch_bounds__(512) void prep_kernel(const float* __restrict__ mat,
                                                   const float* __restrict__ te,
                                                   const float4* __restrict__ W) {
    const int b = blockIdx.x;
    if (b < 100) {
        const int p = b >> 1;
        const int h = (b & 1) * 512 + threadIdx.x;
        if (p == 49) {  // zero padding rows 735..767
            #pragma unroll
            for (int row = RR; row < RPAD; row++) g_Xh[row * HB + h] = __ushort_as_half(0);
            return;
        }
        const int m = p / 7, n = p % 7;
        const float mv = fmaxf(mat[h * 49 + n * 7 + m], 0.f);
        const int rb = m * 7 + n;
        #pragma unroll
        for (int t = 0; t < 15; t++) {
            float s = 1.f + 1.f / (1.f + __expf(-te[h * 15 + t]));
            g_Xh[(t * 49 + rb) * HB + h] = __float2half_rn(s * mv);
        }
    } else {
        const int i = (b - 100) * 512 + threadIdx.x;   // 0 .. HM*HB/8-1
        float4 v0 = W[i * 2];
        float4 v1 = W[i * 2 + 1];
        __half2 h[4];
        h[0] = __floats2half2_rn(v0.x, v0.y);
        h[1] = __floats2half2_rn(v0.z, v0.w);
        h[2] = __floats2half2_rn(v1.x, v1.y);
        h[3] = __floats2half2_rn(v1.z, v1.w);
        *reinterpret_cast<uint4*>(&g_Wh[(size_t)i * 8]) = *reinterpret_cast<uint4*>(h);
    }
}

// ---------------- Kernel 2: fp16 mma.sync GEMM, ldmatrix fragments ----------------
// C[M=8192(hm)][N=768(r)] = g_Wh @ g_Xh^T ; epilogue: relu(C + b[hm]) -> g_Y
#define KTH 32             // K halfs per smem stage
#define KSH 40             // smem row stride in halfs: 80B rows -> conflict-free LDSM/STS
#define KTILES (HB / KTH)  // 32
#define NSTAGE 3
#define STAGE_H (128 * KSH)                 // halfs per array per stage
#define GEMM_DYN (NSTAGE * 2 * STAGE_H * 2) // 61440 bytes

extern __shared__ __half g_sm[];

__global__ __launch_bounds__(256, 2) void gemm_kernel(const float* __restrict__ bias) {
    const int tid  = threadIdx.x;
    const int lane = tid & 31, warp = tid >> 5;
    const int g  = lane >> 2, t4 = lane & 3;
    const int mb = (warp >> 1) * 32;   // warp grid 4(M) x 2(N)
    const int nb = (warp & 1) * 64;
    const int m0 = blockIdx.y * 128;
    const int n0 = blockIdx.x * 128;

    const int lrow = tid >> 1;            // 0..127
    const int lkc  = (tid & 1) * 2;       // 16B chunk pair

    const uint32_t sBase = (uint32_t)__cvta_generic_to_shared(g_sm);

    const __half* Ag = g_Wh + (size_t)(m0 + lrow) * HB;
    const __half* Bg = g_Xh + (size_t)(n0 + lrow) * HB;

    // ldmatrix per-lane address offsets (bytes, relative to stage base)
    const int q  = lane >> 3, rr = lane & 7;
    uint32_t aOff[2], bOff[4];
    {
        const int aRow = (q & 1) * 8 + rr, aK = (q >> 1) * 8;
        const int bN   = (q >> 1) * 8 + rr, bK = (q & 1) * 8;
        #pragma unroll
        for (int mt = 0; mt < 2; mt++)
            aOff[mt] = (uint32_t)(((mb + mt * 16 + aRow) * KSH + aK) * 2);
        #pragma unroll
        for (int p = 0; p < 4; p++)
            bOff[p] = (uint32_t)((STAGE_H + (nb + p * 16 + bN) * KSH + bK) * 2);
    }

    float c[2][8][4];
    #pragma unroll
    for (int i = 0; i < 2; i++)
        #pragma unroll
        for (int j = 0; j < 8; j++)
            #pragma unroll
            for (int qq = 0; qq < 4; qq++) c[i][j][qq] = 0.f;

    auto load_stage = [&](int s, int kt) {
        const int k0 = kt * KTH;
        uint32_t sa = sBase + (uint32_t)(s * (2 * STAGE_H)) * 2u;
        uint32_t sb = sa + (uint32_t)STAGE_H * 2u;
        #pragma unroll
        for (int cch = 0; cch < 2; cch++) {
            int kh = (lkc + cch) * 8;
            cp16(sa + (uint32_t)(lrow * KSH + kh) * 2u, Ag + k0 + kh);
            cp16(sb + (uint32_t)(lrow * KSH + kh) * 2u, Bg + k0 + kh);
        }
        asm volatile("cp.async.commit_group;");
    };

    load_stage(0, 0);
    load_stage(1, 1);

    #pragma unroll 1
    for (int kt = 0; kt < KTILES; kt++) {
        if (kt < KTILES - 2) asm volatile("cp.async.wait_group 1;");
        else                 asm volatile("cp.async.wait_group 0;");
        __syncthreads();
        int cur = kt % NSTAGE;
        if (kt + 2 < KTILES) load_stage((kt + 2) % NSTAGE, kt + 2);

        const uint32_t stBase = sBase + (uint32_t)(cur * (2 * STAGE_H)) * 2u;
        #pragma unroll
        for (int s16 = 0; s16 < 2; s16++) {
            const uint32_t khB = (uint32_t)(s16 * 16 * 2);
            uint32_t a[2][4], b[4][4];
            ldsm4(a[0], stBase + aOff[0] + khB);
            ldsm4(a[1], stBase + aOff[1] + khB);
            #pragma unroll
            for (int p = 0; p < 4; p++)
                ldsm4(b[p], stBase + bOff[p] + khB);
            #pragma unroll
            for (int mt = 0; mt < 2; mt++)
                #pragma unroll
                for (int nt = 0; nt < 8; nt++)
                    mma_f16(c[mt][nt], a[mt], &b[nt >> 1][(nt & 1) * 2]);
        }
    }

    // epilogue: +bias, relu, store Y[hm][r]
    #pragma unroll
    for (int mt = 0; mt < 2; mt++) {
        #pragma unroll
        for (int qq = 0; qq < 2; qq++) {
            int row = m0 + mb + mt * 16 + g + qq * 8;
            float bv = bias[row];
            #pragma unroll
            for (int nt = 0; nt < 8; nt++) {
                int col = n0 + nb + nt * 8 + t4 * 2;
                float2 v;
                v.x = fmaxf(c[mt][nt][qq * 2 + 0] + bv, 0.f);
                v.y = fmaxf(c[mt][nt][qq * 2 + 1] + bv, 0.f);
                *reinterpret_cast<float2*>(&g_Y[(size_t)row * RPAD + col]) = v;
            }
        }
    }
}

// ---------------- Kernel 3: assemble + degree-normalize ----------------
// mixed[hm,1+row,1+col] = Y[hm, (49-7*(row/7)+col)*7 + row%7]
// row 0 / col 0: identity entries at multiples of 7. d = clip(rowsum,1)^-0.5.
__global__ __launch_bounds__(228) void assemble_kernel(float* __restrict__ out) {
    __shared__ float sy[RR + 1];
    __shared__ float sd[NN];
    __shared__ float psum[4][NN + 1];
    __shared__ int   rbase[NN];

    const int tid = threadIdx.x;
    const int jc  = tid % 57;
    const int ty  = tid / 57;
    const int hm  = blockIdx.x;
    const float* yrow = g_Y + (size_t)hm * RPAD;

    for (int r = tid; r < RR; r += 228) sy[r] = yrow[r];
    if (tid > 0 && tid < NN) {
        int row = tid - 1, j = row / 7, n = row % 7;
        rbase[tid] = (49 - 7 * j) * 7 + n;
    }
    __syncthreads();

    {
        float acc = 0.f;
        if (jc > 0) {
            int base = rbase[jc] + ty * 14 * 7;
            #pragma unroll
            for (int cc = 0; cc < 14; cc++) acc += sy[base + cc * 7];
        }
        psum[ty][jc] = acc;
    }
    __syncthreads();

    if (tid < NN) {
        float s;
        if (tid == 0) s = 9.f;
        else {
            s = psum[0][tid] + psum[1][tid] + psum[2][tid] + psum[3][tid];
            if ((tid % 7) == 0) s += 1.f;
        }
        sd[tid] = (s <= 1.f) ? 1.f : rsqrtf(s);
    }
    __syncthreads();

    const size_t ob  = (size_t)hm * OUTN;
    const float  sdj = sd[jc];
    const bool   jc7 = (jc % 7) == 0;
    const int    gcol = (jc - 1) * 7;

    #pragma unroll
    for (int it = 0; it < 15; it++) {
        int i = ty + it * 4;
        if (i >= NN) break;
        float v;
        if (i == 0)        v = jc7 ? sd[0] * sdj : 0.f;
        else if (jc == 0)  v = ((i % 7) == 0) ? sd[i] * sd[0] : 0.f;
        else               v = sd[i] * sdj * sy[rbase[i] + gcol];
        out[ob + i * NN + jc] = v;
    }
}

// ---------------- launch ----------------
extern "C" void kernel_launch(void* const* d_in, const int* in_sizes, int n_in,
                              void* d_out, int out_size) {
    const float* mat = (const float*)d_in[0];
    const float* te  = (const float*)d_in[1];
    const float* W   = (const float*)d_in[2];
    const float* b   = (const float*)d_in[3];
    float* out = (float*)d_out;

    cudaFuncSetAttribute(gemm_kernel, cudaFuncAttributeMaxDynamicSharedMemorySize, GEMM_DYN);

    prep_kernel<<<2148, 512>>>(mat, te, (const float4*)W);
    gemm_kernel<<<dim3(6, 64), 256, GEMM_DYN>>>(b);
    assemble_kernel<<<HM, 228>>>(out);
}